// round 3
// baseline (speedup 1.0000x reference)
#include <cuda_runtime.h>
#include <cuda_bf16.h>
#include <cstdint>
#include <cmath>

// Problem dims
#define BB 64
#define TT 2048
#define DD 256
#define VV 256

// ---------------------------------------------------------------------------
// Device-global scratch (allocation-free per harness rules)
// ---------------------------------------------------------------------------
__device__ float g_EWx[VV * DD];    // EWx[v][e]  = sum_d E[v,d] * Wx_w[e,d]
__device__ float g_EWzs[VV * DD];   // EWzs[v][e] = sigmoid(sum_d E[v,d] * Wz_w[e,d])
__device__ float g_y[(size_t)BB * TT * DD];   // y[b][t][e] = h * gate   (134 MB)

// ---------------------------------------------------------------------------
// Kernel 1: precompute the two 256x256 token tables.
// grid = 256 (v), block = 256 (e)
// ---------------------------------------------------------------------------
__global__ void __launch_bounds__(256) precompute_kernel(
    const float* __restrict__ E,
    const float* __restrict__ Wx,
    const float* __restrict__ Wz)
{
    __shared__ float ev[DD];
    const int v = blockIdx.x;
    const int e = threadIdx.x;
    ev[e] = E[v * DD + e];
    __syncthreads();

    const float* wxr = Wx + e * DD;
    const float* wzr = Wz + e * DD;
    float ax = 0.f, az = 0.f;
#pragma unroll 8
    for (int d = 0; d < DD; d += 4) {
        float4 e4 = *(const float4*)&ev[d];
        float4 x4 = *(const float4*)&wxr[d];
        float4 z4 = *(const float4*)&wzr[d];
        ax = fmaf(e4.x, x4.x, ax); ax = fmaf(e4.y, x4.y, ax);
        ax = fmaf(e4.z, x4.z, ax); ax = fmaf(e4.w, x4.w, ax);
        az = fmaf(e4.x, z4.x, az); az = fmaf(e4.y, z4.y, az);
        az = fmaf(e4.z, z4.z, az); az = fmaf(e4.w, z4.w, az);
    }
    g_EWx[v * DD + e]  = ax;
    g_EWzs[v * DD + e] = 1.0f / (1.0f + expf(-az));
}

// ---------------------------------------------------------------------------
// Kernel 2: Elman recurrence. One CTA per batch element, 512 threads.
// thread tid: e = tid & 255 (output unit), half = tid >> 8 (d-range half).
// Each thread covers d in [half*128, half*128+128):
//     first 64 d's -> weights in registers
//     last  64 d's -> weights in shared memory (float2-packed, [pair][e])
// Dynamic smem layout:
//   [0, 131072)          float2 wsm[2][32][256]     (weights, smem half)
//   [131072, +2048)      float  h[2][256]           (double-buffered state)
//   [+2048, +1024)       float  part[256]           (half-reduction)
//   [..., +8192)         int    tok[2048]           (this batch's tokens)
// ---------------------------------------------------------------------------
#define RNN_SMEM_BYTES (131072 + 2048 + 1024 + 8192)

__global__ void __launch_bounds__(512, 1) recurrence_kernel(
    const int* __restrict__ tokens,
    const float* __restrict__ Wh)
{
    extern __shared__ char smem_raw[];
    float2* wsm  = (float2*)smem_raw;                       // [2*32][256]
    float*  h_s  = (float*)(smem_raw + 131072);             // [2][256]
    float*  part = h_s + 2 * DD;                            // [256]
    int*    toks = (int*)(part + DD);                       // [2048]

    const int b    = blockIdx.x;
    const int tid  = threadIdx.x;
    const int e    = tid & 255;
    const int half = tid >> 8;
    const int dbase = half * 128;

    // Load this batch element's token sequence into smem.
    for (int i = tid; i < TT; i += 512)
        toks[i] = tokens[b * TT + i];

    // Register-resident weights: Wh[e][dbase .. dbase+64)
    float w[64];
    {
        const float* wr = Wh + e * DD + dbase;
#pragma unroll
        for (int i = 0; i < 64; i += 4) {
            float4 t4 = *(const float4*)(wr + i);
            w[i] = t4.x; w[i + 1] = t4.y; w[i + 2] = t4.z; w[i + 3] = t4.w;
        }
    }
    // Smem-resident weights: Wh[e][dbase+64 .. dbase+128), packed as pairs.
    {
        const float* wr = Wh + e * DD + dbase + 64;
        float2* wdst = wsm + half * 32 * DD;
#pragma unroll 4
        for (int q = 0; q < 32; q++) {
            float2 v; v.x = wr[2 * q]; v.y = wr[2 * q + 1];
            wdst[q * DD + e] = v;
        }
    }
    // h0 = 0
    if (tid < DD) { h_s[tid] = 0.f; }
    __syncthreads();

    const float2* wsm_h = wsm + half * 32 * DD;
    float* yout = g_y + (size_t)b * TT * DD;
    int p = 0;

    for (int t = 0; t < TT; t++) {
        const int tok = toks[t];

        // Early-issue the L2-resident table loads (hidden under dot product).
        float wx = 0.f, gt = 0.f;
        if (half == 0) {
            wx = __ldg(&g_EWx[tok * DD + e]);
            gt = __ldg(&g_EWzs[tok * DD + e]);
        }

        // 128-element partial dot product.
        const float* hp = h_s + p * DD + dbase;
        float acc = 0.f;
#pragma unroll
        for (int i = 0; i < 64; i += 4) {           // register weights
            float4 hv = *(const float4*)(hp + i);
            acc = fmaf(w[i],     hv.x, acc);
            acc = fmaf(w[i + 1], hv.y, acc);
            acc = fmaf(w[i + 2], hv.z, acc);
            acc = fmaf(w[i + 3], hv.w, acc);
        }
        const float2* hp2 = (const float2*)(hp + 64);
#pragma unroll
        for (int q = 0; q < 32; q++) {              // smem weights
            float2 wv = wsm_h[q * DD + e];
            float2 hv = hp2[q];
            acc = fmaf(wv.x, hv.x, acc);
            acc = fmaf(wv.y, hv.y, acc);
        }

        if (half) part[e] = acc;
        __syncthreads();

        if (!half) {
            float z  = acc + part[e] + wx;
            float hn = tanhf(z);
            h_s[(p ^ 1) * DD + e] = hn;
            yout[(size_t)t * DD + e] = hn * gt;
        }
        __syncthreads();
        p ^= 1;
    }
}

// ---------------------------------------------------------------------------
// Kernel 3: head GEMM  out[n][v] = sum_d y[n][d] * E[v][d]
// n = b*T + t in [0, 131072), v in [0, 256).
// CTA tile: 128(n) x 128(v), K-tile 16, 8x8 register blocking, 256 threads.
// ---------------------------------------------------------------------------
#define HN 128
#define HV 128
#define HK 16
#define HPAD 4   // smem row pad (row stride 132 floats, 16B-aligned rows)

__global__ void __launch_bounds__(256) head_kernel(
    const float* __restrict__ E,
    float* __restrict__ out)
{
    __shared__ float As[HK][HN + HPAD];   // y, k-major
    __shared__ float Bs[HK][HV + HPAD];   // E, k-major

    const int n0 = blockIdx.x * HN;
    const int v0 = blockIdx.y * HV;
    const int tid = threadIdx.x;
    const int tx = tid & 15;    // v sub-block
    const int ty = tid >> 4;    // n sub-block

    float acc[8][8];
#pragma unroll
    for (int i = 0; i < 8; i++)
#pragma unroll
        for (int j = 0; j < 8; j++) acc[i][j] = 0.f;

    const float* yb = g_y;

    for (int kk = 0; kk < DD; kk += HK) {
#pragma unroll
        for (int r = 0; r < 8; r++) {
            int l = tid + r * 256;          // 0..2047
            int ni = l >> 4;
            int ki = l & 15;
            As[ki][ni] = yb[(size_t)(n0 + ni) * DD + kk + ki];
            Bs[ki][ni] = E[(v0 + ni) * DD + kk + ki];
        }
        __syncthreads();

#pragma unroll
        for (int k = 0; k < HK; k++) {
            float a[8], bv[8];
            *(float4*)(a)     = *(const float4*)&As[k][ty * 8];
            *(float4*)(a + 4) = *(const float4*)&As[k][ty * 8 + 4];
            *(float4*)(bv)     = *(const float4*)&Bs[k][tx * 8];
            *(float4*)(bv + 4) = *(const float4*)&Bs[k][tx * 8 + 4];
#pragma unroll
            for (int i = 0; i < 8; i++)
#pragma unroll
                for (int j = 0; j < 8; j++)
                    acc[i][j] = fmaf(a[i], bv[j], acc[i][j]);
        }
        __syncthreads();
    }

#pragma unroll
    for (int i = 0; i < 8; i++) {
        float* orow = out + (size_t)(n0 + ty * 8 + i) * VV + v0 + tx * 8;
        *(float4*)(orow)     = *(const float4*)&acc[i][0];
        *(float4*)(orow + 4) = *(const float4*)&acc[i][4];
    }
}

// ---------------------------------------------------------------------------
// Launch
// Inputs (metadata order): tokens(int32 [B,T]), E(f32 [V,D]),
//                          Wx_w(f32 [D,D]), Wh_w(f32 [D,D]), Wz_w(f32 [D,D])
// Output: float [B,T,V]
// ---------------------------------------------------------------------------
extern "C" void kernel_launch(void* const* d_in, const int* in_sizes, int n_in,
                              void* d_out, int out_size)
{
    const int*   tokens = (const int*)  d_in[0];
    const float* E      = (const float*)d_in[1];
    const float* Wx_w   = (const float*)d_in[2];
    const float* Wh_w   = (const float*)d_in[3];
    const float* Wz_w   = (const float*)d_in[4];
    float* out = (float*)d_out;

    // Idempotent, non-stream attribute set (needed for 139 KB dynamic smem).
    cudaFuncSetAttribute(recurrence_kernel,
                         cudaFuncAttributeMaxDynamicSharedMemorySize,
                         RNN_SMEM_BYTES);

    precompute_kernel<<<VV, 256>>>(E, Wx_w, Wz_w);
    recurrence_kernel<<<BB, 512, RNN_SMEM_BYTES>>>(tokens, Wh_w);
    head_kernel<<<dim3((BB * TT) / HN, HV ? VV / HV : 1), 256>>>(E, out);
}

// round 5
// speedup vs baseline: 1.2798x; 1.2798x over previous
#include <cuda_runtime.h>
#include <cuda_bf16.h>
#include <cstdint>
#include <cmath>

// Problem dims
#define BB 64
#define TT 2048
#define DD 256
#define VV 256

// ---------------------------------------------------------------------------
// Packed f32x2 helpers (sm_103a). ptxas never auto-fuses these; PTX accepts.
// A b64 register holds (lo=f0, hi=f1); float4 memory layout == two such pairs.
// ---------------------------------------------------------------------------
static __device__ __forceinline__ unsigned long long ffma2(
    unsigned long long a, unsigned long long b, unsigned long long c)
{
    unsigned long long d;
    asm("fma.rn.f32x2 %0, %1, %2, %3;" : "=l"(d) : "l"(a), "l"(b), "l"(c));
    return d;
}
static __device__ __forceinline__ float2 upk2(unsigned long long v)
{
    float2 f;
    asm("mov.b64 {%0, %1}, %2;" : "=f"(f.x), "=f"(f.y) : "l"(v));
    return f;
}
static __device__ __forceinline__ unsigned long long pkdup(float x)
{
    unsigned long long v;
    asm("mov.b64 %0, {%1, %1};" : "=l"(v) : "f"(x));
    return v;
}

// ---------------------------------------------------------------------------
// Device-global scratch (allocation-free per harness rules)
// ---------------------------------------------------------------------------
__device__ float g_EWx[VV * DD];    // EWx[v][e]  = sum_d E[v,d] * Wx_w[e,d]
__device__ float g_EWzs[VV * DD];   // EWzs[v][e] = sigmoid(sum_d E[v,d] * Wz_w[e,d])
__device__ float g_y[(size_t)BB * TT * DD];   // y[b][t][e] = h * gate   (134 MB)

// ---------------------------------------------------------------------------
// Kernel 1: precompute the two 256x256 token tables. grid=256(v), block=256(e)
// ---------------------------------------------------------------------------
__global__ void __launch_bounds__(256) precompute_kernel(
    const float* __restrict__ E,
    const float* __restrict__ Wx,
    const float* __restrict__ Wz)
{
    __shared__ float ev[DD];
    const int v = blockIdx.x;
    const int e = threadIdx.x;
    ev[e] = E[v * DD + e];
    __syncthreads();

    const float* wxr = Wx + e * DD;
    const float* wzr = Wz + e * DD;
    float ax = 0.f, az = 0.f;
#pragma unroll 8
    for (int d = 0; d < DD; d += 4) {
        float4 e4 = *(const float4*)&ev[d];
        float4 x4 = *(const float4*)&wxr[d];
        float4 z4 = *(const float4*)&wzr[d];
        ax = fmaf(e4.x, x4.x, ax); ax = fmaf(e4.y, x4.y, ax);
        ax = fmaf(e4.z, x4.z, ax); ax = fmaf(e4.w, x4.w, ax);
        az = fmaf(e4.x, z4.x, az); az = fmaf(e4.y, z4.y, az);
        az = fmaf(e4.z, z4.z, az); az = fmaf(e4.w, z4.w, az);
    }
    g_EWx[v * DD + e]  = ax;
    g_EWzs[v * DD + e] = 1.0f / (1.0f + expf(-az));
}

// ---------------------------------------------------------------------------
// Kernel 2: Elman recurrence. One CTA per batch element, 256 threads.
// Thread e owns output unit e entirely: no reduction, ONE barrier per step.
//   d in [0,176):    88 packed-pair weights in registers
//   d in [176,256):  20 ulonglong2 (4-float) groups in smem, layout [g][e]
// h read via broadcast ld.shared.v2.u64 (1 wavefront per instruction).
// Dynamic smem: wsm 80KB | h[2][256] 2KB | toks 8KB  = 90KB
// ---------------------------------------------------------------------------
#define RPAIR 88          // register pairs   (176 floats, d 0..175)
#define SQUAD 20          // smem quad groups ( 80 floats, d 176..255)
#define RQ    44          // register ulonglong2 groups (= RPAIR/2)
#define WSM_BYTES (SQUAD * DD * 16)          // 81920
#define RNN_SMEM_BYTES (WSM_BYTES + 2 * DD * 4 + TT * 4)

__global__ void __launch_bounds__(256, 1) recurrence_kernel(
    const int* __restrict__ tokens,
    const float* __restrict__ Wh)
{
    extern __shared__ char smem_raw[];
    ulonglong2* wsm = (ulonglong2*)smem_raw;                 // [SQUAD][256]
    float*      h_s = (float*)(smem_raw + WSM_BYTES);        // [2][256], 16B-aligned
    int*       toks = (int*)(h_s + 2 * DD);                  // [2048]

    const int b = blockIdx.x;
    const int e = threadIdx.x;

    for (int i = e; i < TT; i += 256)
        toks[i] = tokens[b * TT + i];

    // Weights for row e. gmem row is 16B-aligned; ulonglong2 view == f32x2 pairs.
    const ulonglong2* wrow = (const ulonglong2*)(Wh + e * DD);
    unsigned long long w[RPAIR];
#pragma unroll
    for (int j = 0; j < RQ; j++) {
        ulonglong2 v = wrow[j];
        w[2 * j] = v.x; w[2 * j + 1] = v.y;
    }
#pragma unroll
    for (int g = 0; g < SQUAD; g++)
        wsm[g * DD + e] = wrow[RQ + g];

    h_s[e] = 0.f;
    __syncthreads();

    float* yout = g_y + (size_t)b * TT * DD;
    int p = 0;

    for (int t = 0; t < TT; t++) {
        const int tok = toks[t];
        // L2-resident table rows; issued early, hidden under the dot product.
        const float wx = __ldg(&g_EWx[tok * DD + e]);
        const float gt = __ldg(&g_EWzs[tok * DD + e]);

        const ulonglong2* hq = (const ulonglong2*)(h_s + p * DD);  // 64 quads
        unsigned long long a0 = 0ull, a1 = 0ull, a2 = 0ull, a3 = 0ull;

#pragma unroll
        for (int j = 0; j < RQ; j++) {          // register-weight half
            ulonglong2 hv = hq[j];
            a0 = ffma2(w[2 * j],     hv.x, a0);
            a1 = ffma2(w[2 * j + 1], hv.y, a1);
        }
#pragma unroll
        for (int g = 0; g < SQUAD; g++) {       // smem-weight tail
            ulonglong2 wv = wsm[g * DD + e];
            ulonglong2 hv = hq[RQ + g];
            a2 = ffma2(wv.x, hv.x, a2);
            a3 = ffma2(wv.y, hv.y, a3);
        }

        float2 f0 = upk2(a0), f1 = upk2(a1), f2 = upk2(a2), f3 = upk2(a3);
        float z = ((f0.x + f0.y) + (f1.x + f1.y))
                + ((f2.x + f2.y) + (f3.x + f3.y)) + wx;
        float hn = tanhf(z);

        h_s[(p ^ 1) * DD + e] = hn;
        yout[(size_t)t * DD + e] = hn * gt;
        __syncthreads();
        p ^= 1;
    }
}

// ---------------------------------------------------------------------------
// Kernel 3: head GEMM  out[n][v] = sum_d y[n][d] * E[v][d], f32x2 inner loop.
// CTA tile 128x128, K-tile 16, 8x8 per thread (as 8 rows x 4 b64 col-pairs).
// ---------------------------------------------------------------------------
#define HN 128
#define HV 128
#define HK 16
#define HPAD 4   // row stride 132 floats = 528B (16B-aligned rows)

__global__ void __launch_bounds__(256) head_kernel(
    const float* __restrict__ E,
    float* __restrict__ out)
{
    __shared__ float As[HK][HN + HPAD];   // y, k-major
    __shared__ float Bs[HK][HV + HPAD];   // E, k-major

    const int n0 = blockIdx.x * HN;
    const int v0 = blockIdx.y * HV;
    const int tid = threadIdx.x;
    const int tx = tid & 15;    // v sub-block
    const int ty = tid >> 4;    // n sub-block

    unsigned long long acc[8][4];
#pragma unroll
    for (int i = 0; i < 8; i++)
#pragma unroll
        for (int j = 0; j < 4; j++) acc[i][j] = 0ull;

    const float* yb = g_y;

    for (int kk = 0; kk < DD; kk += HK) {
#pragma unroll
        for (int r = 0; r < 8; r++) {
            int l = tid + r * 256;          // 0..2047
            int ni = l >> 4;
            int ki = l & 15;
            As[ki][ni] = yb[(size_t)(n0 + ni) * DD + kk + ki];
            Bs[ki][ni] = E[(v0 + ni) * DD + kk + ki];
        }
        __syncthreads();

#pragma unroll
        for (int k = 0; k < HK; k++) {
            float a[8];
            *(float4*)(a)     = *(const float4*)&As[k][ty * 8];
            *(float4*)(a + 4) = *(const float4*)&As[k][ty * 8 + 4];
            ulonglong2 b01 = *(const ulonglong2*)&Bs[k][tx * 8];      // (b0,b1)(b2,b3)
            ulonglong2 b23 = *(const ulonglong2*)&Bs[k][tx * 8 + 4];  // (b4,b5)(b6,b7)
#pragma unroll
            for (int i = 0; i < 8; i++) {
                unsigned long long ad = pkdup(a[i]);
                acc[i][0] = ffma2(ad, b01.x, acc[i][0]);
                acc[i][1] = ffma2(ad, b01.y, acc[i][1]);
                acc[i][2] = ffma2(ad, b23.x, acc[i][2]);
                acc[i][3] = ffma2(ad, b23.y, acc[i][3]);
            }
        }
        __syncthreads();
    }

#pragma unroll
    for (int i = 0; i < 8; i++) {
        float2 c0 = upk2(acc[i][0]);
        float2 c1 = upk2(acc[i][1]);
        float2 c2 = upk2(acc[i][2]);
        float2 c3 = upk2(acc[i][3]);
        float* orow = out + (size_t)(n0 + ty * 8 + i) * VV + v0 + tx * 8;
        float4 lo; lo.x = c0.x; lo.y = c0.y; lo.z = c1.x; lo.w = c1.y;
        float4 hi; hi.x = c2.x; hi.y = c2.y; hi.z = c3.x; hi.w = c3.y;
        *(float4*)(orow)     = lo;
        *(float4*)(orow + 4) = hi;
    }
}

// ---------------------------------------------------------------------------
// Launch
// Inputs (metadata order): tokens(int32 [B,T]), E(f32 [V,D]),
//                          Wx_w(f32 [D,D]), Wh_w(f32 [D,D]), Wz_w(f32 [D,D])
// Output: float [B,T,V]
// ---------------------------------------------------------------------------
extern "C" void kernel_launch(void* const* d_in, const int* in_sizes, int n_in,
                              void* d_out, int out_size)
{
    const int*   tokens = (const int*)  d_in[0];
    const float* E      = (const float*)d_in[1];
    const float* Wx_w   = (const float*)d_in[2];
    const float* Wh_w   = (const float*)d_in[3];
    const float* Wz_w   = (const float*)d_in[4];
    float* out = (float*)d_out;

    cudaFuncSetAttribute(recurrence_kernel,
                         cudaFuncAttributeMaxDynamicSharedMemorySize,
                         RNN_SMEM_BYTES);

    precompute_kernel<<<VV, 256>>>(E, Wx_w, Wz_w);
    recurrence_kernel<<<BB, 256, RNN_SMEM_BYTES>>>(tokens, Wh_w);
    head_kernel<<<dim3((BB * TT) / HN, VV / HV), 256>>>(E, out);
}

// round 10
// speedup vs baseline: 1.4117x; 1.1030x over previous
#include <cuda_runtime.h>
#include <cuda_bf16.h>
#include <cstdint>
#include <cmath>

// Problem dims
#define BB 64
#define TT 2048
#define DD 256
#define VV 256

// ---------------------------------------------------------------------------
// Packed f32x2 helpers (sm_103a). ptxas never auto-fuses these; PTX accepts.
// A b64 register holds (lo=f0, hi=f1); float4 memory layout == two such pairs.
// ---------------------------------------------------------------------------
static __device__ __forceinline__ unsigned long long ffma2(
    unsigned long long a, unsigned long long b, unsigned long long c)
{
    unsigned long long d;
    asm("fma.rn.f32x2 %0, %1, %2, %3;" : "=l"(d) : "l"(a), "l"(b), "l"(c));
    return d;
}
static __device__ __forceinline__ float2 upk2(unsigned long long v)
{
    float2 f;
    asm("mov.b64 {%0, %1}, %2;" : "=f"(f.x), "=f"(f.y) : "l"(v));
    return f;
}
static __device__ __forceinline__ unsigned long long pkdup(float x)
{
    unsigned long long v;
    asm("mov.b64 %0, {%1, %1};" : "=l"(v) : "f"(x));
    return v;
}

// ---------------------------------------------------------------------------
// Device-global scratch (allocation-free per harness rules)
// ---------------------------------------------------------------------------
__device__ float g_EWx[VV * DD];    // EWx[v][e]  = sum_d E[v,d] * Wx_w[e,d]
__device__ float g_EWzs[VV * DD];   // EWzs[v][e] = sigmoid(sum_d E[v,d] * Wz_w[e,d])
__device__ float g_y[(size_t)BB * TT * DD];   // y[b][t][e] = h * gate   (134 MB)

// ---------------------------------------------------------------------------
// Kernel 1: precompute the two 256x256 token tables. grid=256(v), block=256(e)
// ---------------------------------------------------------------------------
__global__ void __launch_bounds__(256) precompute_kernel(
    const float* __restrict__ E,
    const float* __restrict__ Wx,
    const float* __restrict__ Wz)
{
    __shared__ float ev[DD];
    const int v = blockIdx.x;
    const int e = threadIdx.x;
    ev[e] = E[v * DD + e];
    __syncthreads();

    const float* wxr = Wx + e * DD;
    const float* wzr = Wz + e * DD;
    float ax = 0.f, az = 0.f;
#pragma unroll 8
    for (int d = 0; d < DD; d += 4) {
        float4 e4 = *(const float4*)&ev[d];
        float4 x4 = *(const float4*)&wxr[d];
        float4 z4 = *(const float4*)&wzr[d];
        ax = fmaf(e4.x, x4.x, ax); ax = fmaf(e4.y, x4.y, ax);
        ax = fmaf(e4.z, x4.z, ax); ax = fmaf(e4.w, x4.w, ax);
        az = fmaf(e4.x, z4.x, az); az = fmaf(e4.y, z4.y, az);
        az = fmaf(e4.z, z4.z, az); az = fmaf(e4.w, z4.w, az);
    }
    g_EWx[v * DD + e]  = ax;
    g_EWzs[v * DD + e] = 1.0f / (1.0f + expf(-az));
}

// ---------------------------------------------------------------------------
// Kernel 2: Elman recurrence. One CTA per batch element, 256 threads.
// Thread e owns output unit e entirely: no reduction, ONE barrier per step.
//   d in [0,200):    100 packed-pair weights in registers  (~235 regs total,
//                    safe under the 255 cap — risk-adjusted from 104)
//   d in [200,256):  14 ulonglong2 (4-float) groups in smem, layout [g][e]
// Next step's table rows (wx, gt) prefetched before the barrier.
// Dynamic smem: wsm 56KB | h[2][256] 2KB | toks 8KB  = 66KB
// ---------------------------------------------------------------------------
#define RPAIR 100         // register pairs   (200 floats, d 0..199)
#define SQUAD 14          // smem quad groups ( 56 floats, d 200..255)
#define RQ    50          // register ulonglong2 groups (= RPAIR/2)
#define WSM_BYTES (SQUAD * DD * 16)          // 57344
#define RNN_SMEM_BYTES (WSM_BYTES + 2 * DD * 4 + TT * 4)

__global__ void __launch_bounds__(256, 1) recurrence_kernel(
    const int* __restrict__ tokens,
    const float* __restrict__ Wh)
{
    extern __shared__ char smem_raw[];
    ulonglong2* wsm = (ulonglong2*)smem_raw;                 // [SQUAD][256]
    float*      h_s = (float*)(smem_raw + WSM_BYTES);        // [2][256], 16B-aligned
    int*       toks = (int*)(h_s + 2 * DD);                  // [2048]

    const int b = blockIdx.x;
    const int e = threadIdx.x;

    for (int i = e; i < TT; i += 256)
        toks[i] = tokens[b * TT + i];

    // Weights for row e. gmem row is 16B-aligned; ulonglong2 view == f32x2 pairs.
    const ulonglong2* wrow = (const ulonglong2*)(Wh + e * DD);
    unsigned long long w[RPAIR];
#pragma unroll
    for (int j = 0; j < RQ; j++) {
        ulonglong2 v = wrow[j];
        w[2 * j] = v.x; w[2 * j + 1] = v.y;
    }
#pragma unroll
    for (int g = 0; g < SQUAD; g++)
        wsm[g * DD + e] = wrow[RQ + g];

    h_s[e] = 0.f;
    __syncthreads();

    float* yout = g_y + (size_t)b * TT * DD;
    int p = 0;

    // Prime the table-row prefetch for t = 0.
    int tok0 = toks[0];
    float wx = __ldg(&g_EWx[tok0 * DD + e]);
    float gt = __ldg(&g_EWzs[tok0 * DD + e]);

    for (int t = 0; t < TT; t++) {
        // Prefetch NEXT step's table rows (L2-resident) — fully hidden
        // under this step's dot product + barrier.
        float wx_n = 0.f, gt_n = 0.f;
        if (t + 1 < TT) {
            int tk = toks[t + 1];
            wx_n = __ldg(&g_EWx[tk * DD + e]);
            gt_n = __ldg(&g_EWzs[tk * DD + e]);
        }

        const ulonglong2* hq = (const ulonglong2*)(h_s + p * DD);  // 64 quads
        unsigned long long a0 = 0ull, a1 = 0ull, a2 = 0ull, a3 = 0ull;

#pragma unroll
        for (int j = 0; j < RQ; j++) {          // register-weight bulk
            ulonglong2 hv = hq[j];
            a0 = ffma2(w[2 * j],     hv.x, a0);
            a1 = ffma2(w[2 * j + 1], hv.y, a1);
        }
#pragma unroll
        for (int g = 0; g < SQUAD; g++) {       // smem-weight tail
            ulonglong2 wv = wsm[g * DD + e];
            ulonglong2 hv = hq[RQ + g];
            a2 = ffma2(wv.x, hv.x, a2);
            a3 = ffma2(wv.y, hv.y, a3);
        }

        float2 f0 = upk2(a0), f1 = upk2(a1), f2 = upk2(a2), f3 = upk2(a3);
        float z = ((f0.x + f0.y) + (f1.x + f1.y))
                + ((f2.x + f2.y) + (f3.x + f3.y)) + wx;
        float hn = tanhf(z);

        h_s[(p ^ 1) * DD + e] = hn;
        yout[(size_t)t * DD + e] = hn * gt;
        __syncthreads();
        p ^= 1;
        wx = wx_n; gt = gt_n;
    }
}

// ---------------------------------------------------------------------------
// Kernel 3: head GEMM  out[n][v] = sum_d y[n][d] * E[v][d], f32x2 inner loop.
// CTA tile 128x128, K-tile 16, 8x8 per thread (as 8 rows x 4 b64 col-pairs).
// ---------------------------------------------------------------------------
#define HN 128
#define HV 128
#define HK 16
#define HPAD 4   // row stride 132 floats = 528B (16B-aligned rows)

__global__ void __launch_bounds__(256) head_kernel(
    const float* __restrict__ E,
    float* __restrict__ out)
{
    __shared__ float As[HK][HN + HPAD];   // y, k-major
    __shared__ float Bs[HK][HV + HPAD];   // E, k-major

    const int n0 = blockIdx.x * HN;
    const int v0 = blockIdx.y * HV;
    const int tid = threadIdx.x;
    const int tx = tid & 15;    // v sub-block
    const int ty = tid >> 4;    // n sub-block

    unsigned long long acc[8][4];
#pragma unroll
    for (int i = 0; i < 8; i++)
#pragma unroll
        for (int j = 0; j < 4; j++) acc[i][j] = 0ull;

    const float* yb = g_y;

    for (int kk = 0; kk < DD; kk += HK) {
#pragma unroll
        for (int r = 0; r < 8; r++) {
            int l = tid + r * 256;          // 0..2047
            int ni = l >> 4;
            int ki = l & 15;
            As[ki][ni] = yb[(size_t)(n0 + ni) * DD + kk + ki];
            Bs[ki][ni] = E[(v0 + ni) * DD + kk + ki];
        }
        __syncthreads();

#pragma unroll
        for (int k = 0; k < HK; k++) {
            float a[8];
            *(float4*)(a)     = *(const float4*)&As[k][ty * 8];
            *(float4*)(a + 4) = *(const float4*)&As[k][ty * 8 + 4];
            ulonglong2 b01 = *(const ulonglong2*)&Bs[k][tx * 8];      // (b0,b1)(b2,b3)
            ulonglong2 b23 = *(const ulonglong2*)&Bs[k][tx * 8 + 4];  // (b4,b5)(b6,b7)
#pragma unroll
            for (int i = 0; i < 8; i++) {
                unsigned long long ad = pkdup(a[i]);
                acc[i][0] = ffma2(ad, b01.x, acc[i][0]);
                acc[i][1] = ffma2(ad, b01.y, acc[i][1]);
                acc[i][2] = ffma2(ad, b23.x, acc[i][2]);
                acc[i][3] = ffma2(ad, b23.y, acc[i][3]);
            }
        }
        __syncthreads();
    }

#pragma unroll
    for (int i = 0; i < 8; i++) {
        float2 c0 = upk2(acc[i][0]);
        float2 c1 = upk2(acc[i][1]);
        float2 c2 = upk2(acc[i][2]);
        float2 c3 = upk2(acc[i][3]);
        float* orow = out + (size_t)(n0 + ty * 8 + i) * VV + v0 + tx * 8;
        float4 lo; lo.x = c0.x; lo.y = c0.y; lo.z = c1.x; lo.w = c1.y;
        float4 hi; hi.x = c2.x; hi.y = c2.y; hi.z = c3.x; hi.w = c3.y;
        *(float4*)(orow)     = lo;
        *(float4*)(orow + 4) = hi;
    }
}

// ---------------------------------------------------------------------------
// Launch
// Inputs (metadata order): tokens(int32 [B,T]), E(f32 [V,D]),
//                          Wx_w(f32 [D,D]), Wh_w(f32 [D,D]), Wz_w(f32 [D,D])
// Output: float [B,T,V]
// ---------------------------------------------------------------------------
extern "C" void kernel_launch(void* const* d_in, const int* in_sizes, int n_in,
                              void* d_out, int out_size)
{
    const int*   tokens = (const int*)  d_in[0];
    const float* E      = (const float*)d_in[1];
    const float* Wx_w   = (const float*)d_in[2];
    const float* Wh_w   = (const float*)d_in[3];
    const float* Wz_w   = (const float*)d_in[4];
    float* out = (float*)d_out;

    cudaFuncSetAttribute(recurrence_kernel,
                         cudaFuncAttributeMaxDynamicSharedMemorySize,
                         RNN_SMEM_BYTES);

    precompute_kernel<<<VV, 256>>>(E, Wx_w, Wz_w);
    recurrence_kernel<<<BB, 256, RNN_SMEM_BYTES>>>(tokens, Wh_w);
    head_kernel<<<dim3((BB * TT) / HN, VV / HV), 256>>>(E, out);
}

// round 12
// speedup vs baseline: 1.4420x; 1.0215x over previous
#include <cuda_runtime.h>
#include <cuda_bf16.h>
#include <cstdint>
#include <cmath>

// Problem dims
#define BB 64
#define TT 2048
#define DD 256
#define VV 256

// ---------------------------------------------------------------------------
// Packed f32x2 helpers (sm_103a). ptxas never auto-fuses these; PTX accepts.
// A b64 register holds (lo=f0, hi=f1); float4 memory layout == two such pairs.
// ---------------------------------------------------------------------------
static __device__ __forceinline__ unsigned long long ffma2(
    unsigned long long a, unsigned long long b, unsigned long long c)
{
    unsigned long long d;
    asm("fma.rn.f32x2 %0, %1, %2, %3;" : "=l"(d) : "l"(a), "l"(b), "l"(c));
    return d;
}
static __device__ __forceinline__ float2 upk2(unsigned long long v)
{
    float2 f;
    asm("mov.b64 {%0, %1}, %2;" : "=f"(f.x), "=f"(f.y) : "l"(v));
    return f;
}
static __device__ __forceinline__ unsigned long long pkdup(float x)
{
    unsigned long long v;
    asm("mov.b64 %0, {%1, %1};" : "=l"(v) : "f"(x));
    return v;
}

// ---------------------------------------------------------------------------
// Device-global scratch (allocation-free per harness rules)
// ---------------------------------------------------------------------------
__device__ float g_EWx[VV * DD];    // EWx[v][e]  = sum_d E[v,d] * Wx_w[e,d]
__device__ float g_EWzs[VV * DD];   // EWzs[v][e] = sigmoid(sum_d E[v,d] * Wz_w[e,d])
__device__ float g_y[(size_t)BB * TT * DD];   // y[b][t][e] = h * gate   (134 MB)

// ---------------------------------------------------------------------------
// Kernel 1: precompute the two 256x256 token tables. grid=256(v), block=256(e)
// ---------------------------------------------------------------------------
__global__ void __launch_bounds__(256) precompute_kernel(
    const float* __restrict__ E,
    const float* __restrict__ Wx,
    const float* __restrict__ Wz)
{
    __shared__ float ev[DD];
    const int v = blockIdx.x;
    const int e = threadIdx.x;
    ev[e] = E[v * DD + e];
    __syncthreads();

    const float* wxr = Wx + e * DD;
    const float* wzr = Wz + e * DD;
    float ax = 0.f, az = 0.f;
#pragma unroll 8
    for (int d = 0; d < DD; d += 4) {
        float4 e4 = *(const float4*)&ev[d];
        float4 x4 = *(const float4*)&wxr[d];
        float4 z4 = *(const float4*)&wzr[d];
        ax = fmaf(e4.x, x4.x, ax); ax = fmaf(e4.y, x4.y, ax);
        ax = fmaf(e4.z, x4.z, ax); ax = fmaf(e4.w, x4.w, ax);
        az = fmaf(e4.x, z4.x, az); az = fmaf(e4.y, z4.y, az);
        az = fmaf(e4.z, z4.z, az); az = fmaf(e4.w, z4.w, az);
    }
    g_EWx[v * DD + e]  = ax;
    g_EWzs[v * DD + e] = 1.0f / (1.0f + expf(-az));
}

// ---------------------------------------------------------------------------
// Kernel 2: Elman recurrence. One CTA per batch element, 256 threads.
// Thread e owns output unit e entirely: no reduction, ONE barrier per step.
//   d in [0,208):    104 packed-pair weights in registers (~243 regs total;
//                    RPAIR 100 measured no-spill at ~235 — 8-reg headroom)
//   d in [208,256):  12 ulonglong2 (4-float) groups in smem, layout [g][e]
// Next step's table rows (wx, gt) prefetched before the barrier.
// Dynamic smem: wsm 48KB | h[2][256] 2KB | toks 8KB  = 58KB
// ---------------------------------------------------------------------------
#define RPAIR 104         // register pairs   (208 floats, d 0..207)
#define SQUAD 12          // smem quad groups ( 48 floats, d 208..255)
#define RQ    52          // register ulonglong2 groups (= RPAIR/2)
#define WSM_BYTES (SQUAD * DD * 16)          // 49152
#define RNN_SMEM_BYTES (WSM_BYTES + 2 * DD * 4 + TT * 4)

__global__ void __launch_bounds__(256, 1) recurrence_kernel(
    const int* __restrict__ tokens,
    const float* __restrict__ Wh)
{
    extern __shared__ char smem_raw[];
    ulonglong2* wsm = (ulonglong2*)smem_raw;                 // [SQUAD][256]
    float*      h_s = (float*)(smem_raw + WSM_BYTES);        // [2][256], 16B-aligned
    int*       toks = (int*)(h_s + 2 * DD);                  // [2048]

    const int b = blockIdx.x;
    const int e = threadIdx.x;

    for (int i = e; i < TT; i += 256)
        toks[i] = tokens[b * TT + i];

    // Weights for row e. gmem row is 16B-aligned; ulonglong2 view == f32x2 pairs.
    const ulonglong2* wrow = (const ulonglong2*)(Wh + e * DD);
    unsigned long long w[RPAIR];
#pragma unroll
    for (int j = 0; j < RQ; j++) {
        ulonglong2 v = wrow[j];
        w[2 * j] = v.x; w[2 * j + 1] = v.y;
    }
#pragma unroll
    for (int g = 0; g < SQUAD; g++)
        wsm[g * DD + e] = wrow[RQ + g];

    h_s[e] = 0.f;
    __syncthreads();

    float* yout = g_y + (size_t)b * TT * DD;
    int p = 0;

    // Prime the table-row prefetch for t = 0.
    int tok0 = toks[0];
    float wx = __ldg(&g_EWx[tok0 * DD + e]);
    float gt = __ldg(&g_EWzs[tok0 * DD + e]);

    for (int t = 0; t < TT; t++) {
        // Prefetch NEXT step's table rows (L2-resident) — fully hidden
        // under this step's dot product + barrier.
        float wx_n = 0.f, gt_n = 0.f;
        if (t + 1 < TT) {
            int tk = toks[t + 1];
            wx_n = __ldg(&g_EWx[tk * DD + e]);
            gt_n = __ldg(&g_EWzs[tk * DD + e]);
        }

        const ulonglong2* hq = (const ulonglong2*)(h_s + p * DD);  // 64 quads
        unsigned long long a0 = 0ull, a1 = 0ull, a2 = 0ull, a3 = 0ull;

#pragma unroll
        for (int j = 0; j < RQ; j++) {          // register-weight bulk
            ulonglong2 hv = hq[j];
            a0 = ffma2(w[2 * j],     hv.x, a0);
            a1 = ffma2(w[2 * j + 1], hv.y, a1);
        }
#pragma unroll
        for (int g = 0; g < SQUAD; g++) {       // smem-weight tail
            ulonglong2 wv = wsm[g * DD + e];
            ulonglong2 hv = hq[RQ + g];
            a2 = ffma2(wv.x, hv.x, a2);
            a3 = ffma2(wv.y, hv.y, a3);
        }

        float2 f0 = upk2(a0), f1 = upk2(a1), f2 = upk2(a2), f3 = upk2(a3);
        float z = ((f0.x + f0.y) + (f1.x + f1.y))
                + ((f2.x + f2.y) + (f3.x + f3.y)) + wx;
        float hn = tanhf(z);

        h_s[(p ^ 1) * DD + e] = hn;
        yout[(size_t)t * DD + e] = hn * gt;
        __syncthreads();
        p ^= 1;
        wx = wx_n; gt = gt_n;
    }
}

// ---------------------------------------------------------------------------
// Kernel 3: head GEMM  out[n][v] = sum_d y[n][d] * E[v][d], f32x2 inner loop.
// CTA tile 128x128, K-tile 16, 8x8 per thread (as 8 rows x 4 b64 col-pairs).
// ---------------------------------------------------------------------------
#define HN 128
#define HV 128
#define HK 16
#define HPAD 4   // row stride 132 floats = 528B (16B-aligned rows)

__global__ void __launch_bounds__(256) head_kernel(
    const float* __restrict__ E,
    float* __restrict__ out)
{
    __shared__ float As[HK][HN + HPAD];   // y, k-major
    __shared__ float Bs[HK][HV + HPAD];   // E, k-major

    const int n0 = blockIdx.x * HN;
    const int v0 = blockIdx.y * HV;
    const int tid = threadIdx.x;
    const int tx = tid & 15;    // v sub-block
    const int ty = tid >> 4;    // n sub-block

    unsigned long long acc[8][4];
#pragma unroll
    for (int i = 0; i < 8; i++)
#pragma unroll
        for (int j = 0; j < 4; j++) acc[i][j] = 0ull;

    const float* yb = g_y;

    for (int kk = 0; kk < DD; kk += HK) {
#pragma unroll
        for (int r = 0; r < 8; r++) {
            int l = tid + r * 256;          // 0..2047
            int ni = l >> 4;
            int ki = l & 15;
            As[ki][ni] = yb[(size_t)(n0 + ni) * DD + kk + ki];
            Bs[ki][ni] = E[(v0 + ni) * DD + kk + ki];
        }
        __syncthreads();

#pragma unroll
        for (int k = 0; k < HK; k++) {
            float a[8];
            *(float4*)(a)     = *(const float4*)&As[k][ty * 8];
            *(float4*)(a + 4) = *(const float4*)&As[k][ty * 8 + 4];
            ulonglong2 b01 = *(const ulonglong2*)&Bs[k][tx * 8];      // (b0,b1)(b2,b3)
            ulonglong2 b23 = *(const ulonglong2*)&Bs[k][tx * 8 + 4];  // (b4,b5)(b6,b7)
#pragma unroll
            for (int i = 0; i < 8; i++) {
                unsigned long long ad = pkdup(a[i]);
                acc[i][0] = ffma2(ad, b01.x, acc[i][0]);
                acc[i][1] = ffma2(ad, b01.y, acc[i][1]);
                acc[i][2] = ffma2(ad, b23.x, acc[i][2]);
                acc[i][3] = ffma2(ad, b23.y, acc[i][3]);
            }
        }
        __syncthreads();
    }

#pragma unroll
    for (int i = 0; i < 8; i++) {
        float2 c0 = upk2(acc[i][0]);
        float2 c1 = upk2(acc[i][1]);
        float2 c2 = upk2(acc[i][2]);
        float2 c3 = upk2(acc[i][3]);
        float* orow = out + (size_t)(n0 + ty * 8 + i) * VV + v0 + tx * 8;
        float4 lo; lo.x = c0.x; lo.y = c0.y; lo.z = c1.x; lo.w = c1.y;
        float4 hi; hi.x = c2.x; hi.y = c2.y; hi.z = c3.x; hi.w = c3.y;
        *(float4*)(orow)     = lo;
        *(float4*)(orow + 4) = hi;
    }
}

// ---------------------------------------------------------------------------
// Launch
// Inputs (metadata order): tokens(int32 [B,T]), E(f32 [V,D]),
//                          Wx_w(f32 [D,D]), Wh_w(f32 [D,D]), Wz_w(f32 [D,D])
// Output: float [B,T,V]
// ---------------------------------------------------------------------------
extern "C" void kernel_launch(void* const* d_in, const int* in_sizes, int n_in,
                              void* d_out, int out_size)
{
    const int*   tokens = (const int*)  d_in[0];
    const float* E      = (const float*)d_in[1];
    const float* Wx_w   = (const float*)d_in[2];
    const float* Wh_w   = (const float*)d_in[3];
    const float* Wz_w   = (const float*)d_in[4];
    float* out = (float*)d_out;

    cudaFuncSetAttribute(recurrence_kernel,
                         cudaFuncAttributeMaxDynamicSharedMemorySize,
                         RNN_SMEM_BYTES);

    precompute_kernel<<<VV, 256>>>(E, Wx_w, Wz_w);
    recurrence_kernel<<<BB, 256, RNN_SMEM_BYTES>>>(tokens, Wh_w);
    head_kernel<<<dim3((BB * TT) / HN, VV / HV), 256>>>(E, out);
}